// round 11
// baseline (speedup 1.0000x reference)
#include <cuda_runtime.h>

// mailbox: [N=50000, DEG=32, FEAT=128] float32 -> out[n][f] = mean over deg.
//
// Pure HBM-bound stream (~845MB, zero reuse). R5 baseline: 125.7us, 86.9% DRAM.
// This round:
//  - persistent single-wave grid (148 SMs x 8 blocks = 1184 blocks, grid-stride)
//    eliminates ~5 wave transitions (~2360cyc each) and per-wave tail drain
//  - __ldcs / __stcs streaming hints: data is read/written exactly once, so
//    evict-first keeps L2 from thrashing sector state on a pure stream
//
// One thread per (node, float4-column): warp = exactly one 512B neighbor row,
// every LDG.128 a full coalesced line; fully-unrolled deg loop for MLP.

#define N_NODES 50000
#define MAX_DEG 32
#define FEAT4   32                      // 128 floats / 4
#define TOTAL4  (N_NODES * FEAT4)       // 1,600,000 float4 outputs

#define NUM_SMS    148
#define BLOCKS_SM  8
#define THREADS    256
#define GRID       (NUM_SMS * BLOCKS_SM)   // 1184 blocks = exactly one wave

__global__ void __launch_bounds__(THREADS, BLOCKS_SM)
mean_agg_kernel(const float4* __restrict__ mailbox, float4* __restrict__ out) {
    const float inv = 1.0f / (float)MAX_DEG;
    const int stride = GRID * THREADS;

    for (int idx = blockIdx.x * THREADS + threadIdx.x; idx < TOTAL4; idx += stride) {
        int n  = idx >> 5;          // / FEAT4
        int f4 = idx & 31;          // % FEAT4

        const float4* p = mailbox + ((long long)n * (MAX_DEG * FEAT4)) + f4;

        float4 acc = make_float4(0.f, 0.f, 0.f, 0.f);
#pragma unroll
        for (int d = 0; d < MAX_DEG; ++d) {
            float4 v = __ldcs(&p[d * FEAT4]);   // evict-first: read-once stream
            acc.x += v.x;
            acc.y += v.y;
            acc.z += v.z;
            acc.w += v.w;
        }

        acc.x *= inv; acc.y *= inv; acc.z *= inv; acc.w *= inv;
        __stcs(&out[idx], acc);                  // streaming store
    }
}

extern "C" void kernel_launch(void* const* d_in, const int* in_sizes, int n_in,
                              void* d_out, int out_size) {
    const float4* mailbox = (const float4*)d_in[0];
    float4* out = (float4*)d_out;
    mean_agg_kernel<<<GRID, THREADS>>>(mailbox, out);
}

// round 13
// speedup vs baseline: 1.0179x; 1.0179x over previous
#include <cuda_runtime.h>

// mailbox: [N=50000, DEG=32, FEAT=128] float32 -> out[n][f] = mean over deg.
//
// Pure HBM-bound stream, ~845MB total, zero reuse. Measured ceiling so far:
// 6.88 TB/s (86.9% of spec) with the flat-grid R5 kernel. R11 showed the
// persistent grid + __ldcs both slightly hurt (127.7us) -> reverted.
//
// This round = R5 config exactly (6250 blocks x 256 thr, one thread per
// (node, float4-col), warp = one 512B neighbor row, fully-unrolled deg loop)
// with ONE change: __ldcg loads (L2-cached, no L1 allocate) since every byte
// is read exactly once -- skips L1 fill work on a zero-reuse stream.

#define N_NODES 50000
#define MAX_DEG 32
#define FEAT4   32                      // 128 floats / 4
#define TOTAL4  (N_NODES * FEAT4)       // 1,600,000 float4 outputs

__global__ void __launch_bounds__(256, 8)
mean_agg_kernel(const float4* __restrict__ mailbox, float4* __restrict__ out) {
    int idx = blockIdx.x * blockDim.x + threadIdx.x;   // n * FEAT4 + f4
    if (idx >= TOTAL4) return;

    int n  = idx >> 5;          // / FEAT4
    int f4 = idx & 31;          // % FEAT4

    const float4* p = mailbox + ((long long)n * (MAX_DEG * FEAT4)) + f4;

    float4 acc = make_float4(0.f, 0.f, 0.f, 0.f);
#pragma unroll
    for (int d = 0; d < MAX_DEG; ++d) {
        float4 v = __ldcg(&p[d * FEAT4]);   // read-once: L2 only, no L1 fill
        acc.x += v.x;
        acc.y += v.y;
        acc.z += v.z;
        acc.w += v.w;
    }

    const float inv = 1.0f / (float)MAX_DEG;
    acc.x *= inv; acc.y *= inv; acc.z *= inv; acc.w *= inv;
    out[idx] = acc;
}

extern "C" void kernel_launch(void* const* d_in, const int* in_sizes, int n_in,
                              void* d_out, int out_size) {
    const float4* mailbox = (const float4*)d_in[0];
    float4* out = (float4*)d_out;
    const int threads = 256;
    const int blocks = (TOTAL4 + threads - 1) / threads;  // 6250
    mean_agg_kernel<<<blocks, threads>>>(mailbox, out);
}

// round 14
// speedup vs baseline: 1.0318x; 1.0137x over previous
#include <cuda_runtime.h>

// mailbox: [N=50000, DEG=32, FEAT=128] float32 -> out[n][f] = mean over deg.
//
// Pure HBM-bound stream, ~845MB, zero reuse. Converged design: one thread per
// (node, float4-col); a warp covers exactly one 512B neighbor row so every
// LDG.128 is a full coalesced line; fully-unrolled deg loop gives MLP=32.
// __ldcg: read-once stream, L2-only, no L1 allocate (R13: best, 87.1% DRAM).
//
// R14 micro-tweaks vs R13 (last untested knobs):
//  - block=512 (same 2048 thr/SM occupancy, half the block-dispatch events)
//  - two accumulator chains (free; removes any load-consume serialization)

#define N_NODES 50000
#define MAX_DEG 32
#define FEAT4   32                      // 128 floats / 4
#define TOTAL4  (N_NODES * FEAT4)       // 1,600,000 float4 outputs

__global__ void __launch_bounds__(512, 4)
mean_agg_kernel(const float4* __restrict__ mailbox, float4* __restrict__ out) {
    int idx = blockIdx.x * blockDim.x + threadIdx.x;   // n * FEAT4 + f4
    if (idx >= TOTAL4) return;

    int n  = idx >> 5;          // / FEAT4
    int f4 = idx & 31;          // % FEAT4

    const float4* p = mailbox + ((long long)n * (MAX_DEG * FEAT4)) + f4;

    // two independent accumulator chains over even/odd neighbors
    float4 a0 = make_float4(0.f, 0.f, 0.f, 0.f);
    float4 a1 = make_float4(0.f, 0.f, 0.f, 0.f);
#pragma unroll
    for (int d = 0; d < MAX_DEG; d += 2) {
        float4 v0 = __ldcg(&p[(d + 0) * FEAT4]);
        float4 v1 = __ldcg(&p[(d + 1) * FEAT4]);
        a0.x += v0.x; a0.y += v0.y; a0.z += v0.z; a0.w += v0.w;
        a1.x += v1.x; a1.y += v1.y; a1.z += v1.z; a1.w += v1.w;
    }

    const float inv = 1.0f / (float)MAX_DEG;
    float4 acc;
    acc.x = (a0.x + a1.x) * inv;
    acc.y = (a0.y + a1.y) * inv;
    acc.z = (a0.z + a1.z) * inv;
    acc.w = (a0.w + a1.w) * inv;
    out[idx] = acc;
}

extern "C" void kernel_launch(void* const* d_in, const int* in_sizes, int n_in,
                              void* d_out, int out_size) {
    const float4* mailbox = (const float4*)d_in[0];
    float4* out = (float4*)d_out;
    const int threads = 512;
    const int blocks = (TOTAL4 + threads - 1) / threads;  // 3125
    mean_agg_kernel<<<blocks, threads>>>(mailbox, out);
}